// round 5
// baseline (speedup 1.0000x reference)
#include <cuda_runtime.h>
#include <cstdint>

// ---------------------------------------------------------------------------
// MultiHeadSelfAttention: x[4,2048,1024] -> out[4,2048,1024]
//   qkv  = x @ w_qkv^T          (8192 x 3072, K=1024)   -> mma.sync tf32
//   attn = flash attention       heads=16, hd=64, scale=1/32 -> fp32
//   out  = attn @ w_out^T + b    (8192 x 1024, K=1024)   -> mma.sync tf32
// tcgen05 is unavailable (harness compiles at virtual compute_103), so the
// tensor path uses classic HMMA via mma.sync.
// ---------------------------------------------------------------------------

#define BATCH 4
#define SEQ   2048
#define DIM   1024
#define HEADS 16
#define HDIM  64
#define QK_SCALE 0.03125f
#define ROWS_TOTAL (BATCH * SEQ)   // 8192

__device__ float g_qkv[ROWS_TOTAL * 3 * DIM];   // 96 MB scratch
__device__ float g_attn[ROWS_TOTAL * DIM];      // 32 MB scratch

__device__ __forceinline__ uint32_t tf32u(float x) {
    uint32_t u;
    asm("cvt.rna.tf32.f32 %0, %1;" : "=r"(u) : "f"(x));
    return u;
}

__device__ __forceinline__ void mma16n8k8(float* c, const uint32_t* a,
                                          const uint32_t* b) {
    asm volatile(
        "mma.sync.aligned.m16n8k8.row.col.f32.tf32.tf32.f32 "
        "{%0,%1,%2,%3}, {%4,%5,%6,%7}, {%8,%9}, {%0,%1,%2,%3};"
        : "+f"(c[0]), "+f"(c[1]), "+f"(c[2]), "+f"(c[3])
        : "r"(a[0]), "r"(a[1]), "r"(a[2]), "r"(a[3]), "r"(b[0]), "r"(b[1]));
}

// ============================================================================
// tf32 tensor-core GEMM: C[M,N] = A[M,K] @ B[N,K]^T (+ bias)
// Block 128x128, 8 warps in 4(m) x 2(n), warp tile 32x64, BK=32.
// SMEM: As[128][36], Bs[128][36] (float, tf32 bits), double buffered.
// ============================================================================
#define BK 32
#define SSTR 36
#define TILE_F (128 * SSTR)
#define GEMM_SMEM_BYTES (2 * 2 * TILE_F * 4)   // 2 bufs x (A+B) = 73728 B

template <bool BIAS>
__global__ __launch_bounds__(256, 2) void gemm_mma(
    const float* __restrict__ A, const float* __restrict__ B,
    const float* __restrict__ bias, float* __restrict__ C, int N, int K)
{
    extern __shared__ float smf[];
    float* As[2] = {smf,             smf + 2 * TILE_F};
    float* Bs[2] = {smf + TILE_F,    smf + 3 * TILE_F};

    const int tid  = threadIdx.x;
    const int wid  = tid >> 5;
    const int lane = tid & 31;
    const int wm   = wid & 3;            // warp row (32 rows)
    const int wn   = wid >> 2;           // warp col (64 cols)
    const int grp  = lane >> 2;          // 0..7
    const int quad = lane & 3;           // 0..3

    const int m0 = blockIdx.y * 128;
    const int n0 = blockIdx.x * 128;
    const float* gA = A + (size_t)m0 * K;
    const float* gB = B + (size_t)n0 * K;
    const int NC = K / BK;

    // global-load mapping: 4 float4 per thread per tile
    const int lrow = tid >> 1;                 // 0..127
    const int lc0  = (tid & 1) * 16;           // 0 or 16 (float index)

    float acc[2][8][4];
    #pragma unroll
    for (int i = 0; i < 2; i++)
        #pragma unroll
        for (int j = 0; j < 8; j++)
            #pragma unroll
            for (int q = 0; q < 4; q++) acc[i][j][q] = 0.f;

    // ---- prologue: load chunk 0 ----
    {
        const float* ap = gA + (size_t)lrow * K + lc0;
        const float* bp = gB + (size_t)lrow * K + lc0;
        float* as = As[0] + lrow * SSTR + lc0;
        float* bs = Bs[0] + lrow * SSTR + lc0;
        #pragma unroll
        for (int v = 0; v < 4; v++) {
            float4 a4 = *(const float4*)(ap + v * 4);
            float4 b4 = *(const float4*)(bp + v * 4);
            ((uint32_t*)as)[v * 4 + 0] = tf32u(a4.x);
            ((uint32_t*)as)[v * 4 + 1] = tf32u(a4.y);
            ((uint32_t*)as)[v * 4 + 2] = tf32u(a4.z);
            ((uint32_t*)as)[v * 4 + 3] = tf32u(a4.w);
            ((uint32_t*)bs)[v * 4 + 0] = tf32u(b4.x);
            ((uint32_t*)bs)[v * 4 + 1] = tf32u(b4.y);
            ((uint32_t*)bs)[v * 4 + 2] = tf32u(b4.z);
            ((uint32_t*)bs)[v * 4 + 3] = tf32u(b4.w);
        }
    }
    __syncthreads();

    for (int c = 0; c < NC; c++) {
        const int p = c & 1;

        // prefetch next chunk into registers
        float4 pa[2], pb[2];
        if (c + 1 < NC) {
            const float* ap = gA + (size_t)lrow * K + (c + 1) * BK + lc0;
            const float* bp = gB + (size_t)lrow * K + (c + 1) * BK + lc0;
            #pragma unroll
            for (int v = 0; v < 2; v++) {
                pa[v] = *(const float4*)(ap + v * 8 + (v ? 4 : 0));
            }
            // load all 4 float4s (use two arrays of 2 to keep regs tight)
            pa[0] = *(const float4*)(ap + 0);
            pa[1] = *(const float4*)(ap + 4);
            pb[0] = *(const float4*)(ap + 8);
            pb[1] = *(const float4*)(ap + 12);
            // B handled below after compute (reload; L1-hit)
            (void)bp;
        }

        // ---- compute chunk c ----
        const uint32_t* as = (const uint32_t*)(As[p]);
        const uint32_t* bs = (const uint32_t*)(Bs[p]);
        #pragma unroll
        for (int ks = 0; ks < 4; ks++) {
            const int k = ks * 8;
            uint32_t af[2][4];
            #pragma unroll
            for (int mt = 0; mt < 2; mt++) {
                int r0 = wm * 32 + mt * 16 + grp;
                af[mt][0] = as[r0 * SSTR + k + quad];
                af[mt][1] = as[(r0 + 8) * SSTR + k + quad];
                af[mt][2] = as[r0 * SSTR + k + 4 + quad];
                af[mt][3] = as[(r0 + 8) * SSTR + k + 4 + quad];
            }
            #pragma unroll
            for (int nt = 0; nt < 8; nt++) {
                int ncol = wn * 64 + nt * 8 + grp;
                uint32_t bf[2];
                bf[0] = bs[ncol * SSTR + k + quad];
                bf[1] = bs[ncol * SSTR + k + 4 + quad];
                mma16n8k8(acc[0][nt], af[0], bf);
                mma16n8k8(acc[1][nt], af[1], bf);
            }
        }

        // ---- store prefetched chunk into other buffer ----
        if (c + 1 < NC) {
            float* asw = As[1 - p] + lrow * SSTR + lc0;
            float* bsw = Bs[1 - p] + lrow * SSTR + lc0;
            ((uint32_t*)asw)[0] = tf32u(pa[0].x); ((uint32_t*)asw)[1] = tf32u(pa[0].y);
            ((uint32_t*)asw)[2] = tf32u(pa[0].z); ((uint32_t*)asw)[3] = tf32u(pa[0].w);
            ((uint32_t*)asw)[4] = tf32u(pa[1].x); ((uint32_t*)asw)[5] = tf32u(pa[1].y);
            ((uint32_t*)asw)[6] = tf32u(pa[1].z); ((uint32_t*)asw)[7] = tf32u(pa[1].w);
            ((uint32_t*)asw)[8]  = tf32u(pb[0].x); ((uint32_t*)asw)[9]  = tf32u(pb[0].y);
            ((uint32_t*)asw)[10] = tf32u(pb[0].z); ((uint32_t*)asw)[11] = tf32u(pb[0].w);
            ((uint32_t*)asw)[12] = tf32u(pb[1].x); ((uint32_t*)asw)[13] = tf32u(pb[1].y);
            ((uint32_t*)asw)[14] = tf32u(pb[1].z); ((uint32_t*)asw)[15] = tf32u(pb[1].w);
            // B tile: straight load (L2/L1 resident for weights)
            const float* bp = gB + (size_t)lrow * K + (c + 1) * BK + lc0;
            #pragma unroll
            for (int v = 0; v < 4; v++) {
                float4 b4 = *(const float4*)(bp + v * 4);
                ((uint32_t*)bsw)[v * 4 + 0] = tf32u(b4.x);
                ((uint32_t*)bsw)[v * 4 + 1] = tf32u(b4.y);
                ((uint32_t*)bsw)[v * 4 + 2] = tf32u(b4.z);
                ((uint32_t*)bsw)[v * 4 + 3] = tf32u(b4.w);
            }
        }
        __syncthreads();
    }

    // ---- epilogue ----
    #pragma unroll
    for (int mt = 0; mt < 2; mt++) {
        int r0 = m0 + wm * 32 + mt * 16 + grp;
        #pragma unroll
        for (int nt = 0; nt < 8; nt++) {
            int col = n0 + wn * 64 + nt * 8 + 2 * quad;
            float b0 = 0.f, b1 = 0.f;
            if (BIAS) { b0 = bias[col]; b1 = bias[col + 1]; }
            float2 o0 = {acc[mt][nt][0] + b0, acc[mt][nt][1] + b1};
            float2 o1 = {acc[mt][nt][2] + b0, acc[mt][nt][3] + b1};
            *(float2*)&C[(size_t)r0 * N + col] = o0;
            *(float2*)&C[(size_t)(r0 + 8) * N + col] = o1;
        }
    }
}

// ============================================================================
// Flash attention (fp32, online softmax) — unchanged from R1.
// ============================================================================
#define TSTR 68
#define TILE_FLOATS (64 * TSTR)

__global__ __launch_bounds__(256) void attn_kernel(
    const float* __restrict__ qkv, float* __restrict__ out)
{
    extern __shared__ float sm[];
    float* Qs = sm;
    float* Ks = Qs + TILE_FLOATS;
    float* Vs = Ks + TILE_FLOATS;
    float* Ss = Vs + TILE_FLOATS;
    float* m_s = Ss + TILE_FLOATS;
    float* l_s = m_s + 64;
    float* al_s = l_s + 64;
    float* red = al_s + 64;

    const int b  = blockIdx.z;
    const int h  = blockIdx.y;
    const int q0 = blockIdx.x * 64;

    const int tid = threadIdx.x;
    const int tx = tid & 15;
    const int ty = tid >> 4;
    const int row = tid & 63;
    const int seg = tid >> 6;

    const float* qbase = qkv + ((size_t)(b * SEQ + q0)) * (3 * DIM) + h * HDIM;
    for (int i = tid; i < 64 * 16; i += 256) {
        int r = i >> 4;
        int c4 = (i & 15) << 2;
        float4 v = *(const float4*)(qbase + (size_t)r * (3 * DIM) + c4);
        Qs[(c4 + 0) * TSTR + r] = v.x * QK_SCALE;
        Qs[(c4 + 1) * TSTR + r] = v.y * QK_SCALE;
        Qs[(c4 + 2) * TSTR + r] = v.z * QK_SCALE;
        Qs[(c4 + 3) * TSTR + r] = v.w * QK_SCALE;
    }
    if (tid < 64) { m_s[tid] = -1e30f; l_s[tid] = 0.f; }

    float acc[4][4] = {};
    __syncthreads();

    for (int kt = 0; kt < SEQ / 64; kt++) {
        const int k0 = kt * 64;
        const float* kbase = qkv + ((size_t)(b * SEQ + k0)) * (3 * DIM) + DIM + h * HDIM;
        const float* vbase = kbase + DIM;

        for (int i = tid; i < 64 * 16; i += 256) {
            int r = i >> 4;
            int c4 = (i & 15) << 2;
            float4 kv = *(const float4*)(kbase + (size_t)r * (3 * DIM) + c4);
            Ks[(c4 + 0) * TSTR + r] = kv.x;
            Ks[(c4 + 1) * TSTR + r] = kv.y;
            Ks[(c4 + 2) * TSTR + r] = kv.z;
            Ks[(c4 + 3) * TSTR + r] = kv.w;
            float4 vv = *(const float4*)(vbase + (size_t)r * (3 * DIM) + c4);
            *(float4*)&Vs[r * TSTR + c4] = vv;
        }
        __syncthreads();

        float s[4][4] = {};
        #pragma unroll 8
        for (int k = 0; k < 64; k++) {
            float4 qa = *(const float4*)&Qs[k * TSTR + ty * 4];
            float4 kb = *(const float4*)&Ks[k * TSTR + tx * 4];
            float qr[4] = {qa.x, qa.y, qa.z, qa.w};
            float kr[4] = {kb.x, kb.y, kb.z, kb.w};
            #pragma unroll
            for (int i = 0; i < 4; i++)
                #pragma unroll
                for (int j = 0; j < 4; j++)
                    s[i][j] = fmaf(qr[i], kr[j], s[i][j]);
        }
        #pragma unroll
        for (int j = 0; j < 4; j++) {
            float4 o; o.x = s[0][j]; o.y = s[1][j]; o.z = s[2][j]; o.w = s[3][j];
            *(float4*)&Ss[(tx * 4 + j) * TSTR + ty * 4] = o;
        }
        __syncthreads();

        float lm = -1e30f;
        #pragma unroll
        for (int c = 0; c < 16; c++)
            lm = fmaxf(lm, Ss[(seg * 16 + c) * TSTR + row]);
        red[seg * 64 + row] = lm;
        __syncthreads();
        if (tid < 64) {
            float mt = fmaxf(fmaxf(red[tid], red[64 + tid]),
                             fmaxf(red[128 + tid], red[192 + tid]));
            float mold = m_s[tid];
            float mnew = fmaxf(mold, mt);
            m_s[tid]  = mnew;
            al_s[tid] = __expf(mold - mnew);
        }
        __syncthreads();

        float mnew = m_s[row];
        float ls = 0.f;
        #pragma unroll
        for (int c = 0; c < 16; c++) {
            int idx = (seg * 16 + c) * TSTR + row;
            float p = expf(Ss[idx] - mnew);
            Ss[idx] = p;
            ls += p;
        }
        red[seg * 64 + row] = ls;
        __syncthreads();
        if (tid < 64) {
            l_s[tid] = l_s[tid] * al_s[tid]
                     + red[tid] + red[64 + tid] + red[128 + tid] + red[192 + tid];
        }
        __syncthreads();

        float al[4];
        #pragma unroll
        for (int i = 0; i < 4; i++) al[i] = al_s[ty * 4 + i];
        #pragma unroll
        for (int i = 0; i < 4; i++)
            #pragma unroll
            for (int j = 0; j < 4; j++)
                acc[i][j] *= al[i];

        #pragma unroll 8
        for (int k = 0; k < 64; k++) {
            float4 pa = *(const float4*)&Ss[k * TSTR + ty * 4];
            float4 vb = *(const float4*)&Vs[k * TSTR + tx * 4];
            float pr[4] = {pa.x, pa.y, pa.z, pa.w};
            float vr[4] = {vb.x, vb.y, vb.z, vb.w};
            #pragma unroll
            for (int i = 0; i < 4; i++)
                #pragma unroll
                for (int j = 0; j < 4; j++)
                    acc[i][j] = fmaf(pr[i], vr[j], acc[i][j]);
        }
        __syncthreads();
    }

    #pragma unroll
    for (int i = 0; i < 4; i++) {
        float inv = 1.f / l_s[ty * 4 + i];
        float4 o;
        o.x = acc[i][0] * inv; o.y = acc[i][1] * inv;
        o.z = acc[i][2] * inv; o.w = acc[i][3] * inv;
        *(float4*)&out[(size_t)(b * SEQ + q0 + ty * 4 + i) * DIM + h * HDIM + tx * 4] = o;
    }
}

// ============================================================================
extern "C" void kernel_launch(void* const* d_in, const int* in_sizes, int n_in,
                              void* d_out, int out_size)
{
    const float* x     = (const float*)d_in[0];
    const float* w_qkv = (const float*)d_in[1];
    const float* w_out = (const float*)d_in[2];
    const float* b_out = (const float*)d_in[3];
    float* out = (float*)d_out;

    float* qkv = nullptr;
    float* att = nullptr;
    cudaGetSymbolAddress((void**)&qkv, g_qkv);
    cudaGetSymbolAddress((void**)&att, g_attn);

    const int attn_smem = (4 * TILE_FLOATS + 3 * 64 + 4 * 64) * (int)sizeof(float);
    cudaFuncSetAttribute(attn_kernel, cudaFuncAttributeMaxDynamicSharedMemorySize,
                         attn_smem);
    cudaFuncSetAttribute(gemm_mma<false>, cudaFuncAttributeMaxDynamicSharedMemorySize,
                         GEMM_SMEM_BYTES);
    cudaFuncSetAttribute(gemm_mma<true>, cudaFuncAttributeMaxDynamicSharedMemorySize,
                         GEMM_SMEM_BYTES);

    // 1) qkv = x @ w_qkv^T : M=8192, N=3072, K=1024
    {
        dim3 grid(3 * DIM / 128, ROWS_TOTAL / 128);
        gemm_mma<false><<<grid, 256, GEMM_SMEM_BYTES>>>(x, w_qkv, nullptr, qkv,
                                                        3 * DIM, DIM);
    }
    // 2) flash attention
    {
        dim3 grid(SEQ / 64, HEADS, BATCH);
        attn_kernel<<<grid, 256, attn_smem>>>(qkv, att);
    }
    // 3) out = att @ w_out^T + b_out : M=8192, N=1024, K=1024
    {
        dim3 grid(DIM / 128, ROWS_TOTAL / 128);
        gemm_mma<true><<<grid, 256, GEMM_SMEM_BYTES>>>(att, w_out, b_out, out,
                                                       DIM, DIM);
    }
}

// round 6
// speedup vs baseline: 1.0014x; 1.0014x over previous
#include <cuda_runtime.h>
#include <cstdint>

// ---------------------------------------------------------------------------
// MultiHeadSelfAttention: x[4,2048,1024] -> out[4,2048,1024]
//   qkv  = x @ w_qkv^T          (8192 x 3072, K=1024)   -> mma.sync tf32
//   attn = flash attention       heads=16, hd=64, scale=1/32 -> fp32
//   out  = attn @ w_out^T + b    (8192 x 1024, K=1024)   -> mma.sync tf32
// tcgen05 is unavailable (harness compiles at virtual compute_103), so the
// tensor path uses classic HMMA via mma.sync.
// ---------------------------------------------------------------------------

#define BATCH 4
#define SEQ   2048
#define DIM   1024
#define HEADS 16
#define HDIM  64
#define QK_SCALE 0.03125f
#define ROWS_TOTAL (BATCH * SEQ)   // 8192

__device__ float g_qkv[ROWS_TOTAL * 3 * DIM];   // 96 MB scratch
__device__ float g_attn[ROWS_TOTAL * DIM];      // 32 MB scratch

__device__ __forceinline__ uint32_t tf32u(float x) {
    uint32_t u;
    asm("cvt.rna.tf32.f32 %0, %1;" : "=r"(u) : "f"(x));
    return u;
}

__device__ __forceinline__ void mma16n8k8(float* c, const uint32_t* a,
                                          const uint32_t* b) {
    asm volatile(
        "mma.sync.aligned.m16n8k8.row.col.f32.tf32.tf32.f32 "
        "{%0,%1,%2,%3}, {%4,%5,%6,%7}, {%8,%9}, {%0,%1,%2,%3};"
        : "+f"(c[0]), "+f"(c[1]), "+f"(c[2]), "+f"(c[3])
        : "r"(a[0]), "r"(a[1]), "r"(a[2]), "r"(a[3]), "r"(b[0]), "r"(b[1]));
}

// ============================================================================
// tf32 tensor-core GEMM: C[M,N] = A[M,K] @ B[N,K]^T (+ bias)
// Block 128x128, 8 warps in 4(m) x 2(n), warp tile 32x64, BK=32.
// SMEM: As[128][36], Bs[128][36] (float, tf32 bits), double buffered.
// ============================================================================
#define BK 32
#define SSTR 36
#define TILE_F (128 * SSTR)
#define GEMM_SMEM_BYTES (2 * 2 * TILE_F * 4)   // 2 bufs x (A+B) = 73728 B

template <bool BIAS>
__global__ __launch_bounds__(256, 2) void gemm_mma(
    const float* __restrict__ A, const float* __restrict__ B,
    const float* __restrict__ bias, float* __restrict__ C, int N, int K)
{
    extern __shared__ float smf[];
    float* As[2] = {smf,             smf + 2 * TILE_F};
    float* Bs[2] = {smf + TILE_F,    smf + 3 * TILE_F};

    const int tid  = threadIdx.x;
    const int wid  = tid >> 5;
    const int lane = tid & 31;
    const int wm   = wid & 3;            // warp row (32 rows)
    const int wn   = wid >> 2;           // warp col (64 cols)
    const int grp  = lane >> 2;          // 0..7
    const int quad = lane & 3;           // 0..3

    const int m0 = blockIdx.y * 128;
    const int n0 = blockIdx.x * 128;
    const float* gA = A + (size_t)m0 * K;
    const float* gB = B + (size_t)n0 * K;
    const int NC = K / BK;

    // global-load mapping: 4 float4 per thread per tile
    const int lrow = tid >> 1;                 // 0..127
    const int lc0  = (tid & 1) * 16;           // 0 or 16 (float index)

    float acc[2][8][4];
    #pragma unroll
    for (int i = 0; i < 2; i++)
        #pragma unroll
        for (int j = 0; j < 8; j++)
            #pragma unroll
            for (int q = 0; q < 4; q++) acc[i][j][q] = 0.f;

    // ---- prologue: load chunk 0 ----
    {
        const float* ap = gA + (size_t)lrow * K + lc0;
        const float* bp = gB + (size_t)lrow * K + lc0;
        float* as = As[0] + lrow * SSTR + lc0;
        float* bs = Bs[0] + lrow * SSTR + lc0;
        #pragma unroll
        for (int v = 0; v < 4; v++) {
            float4 a4 = *(const float4*)(ap + v * 4);
            float4 b4 = *(const float4*)(bp + v * 4);
            ((uint32_t*)as)[v * 4 + 0] = tf32u(a4.x);
            ((uint32_t*)as)[v * 4 + 1] = tf32u(a4.y);
            ((uint32_t*)as)[v * 4 + 2] = tf32u(a4.z);
            ((uint32_t*)as)[v * 4 + 3] = tf32u(a4.w);
            ((uint32_t*)bs)[v * 4 + 0] = tf32u(b4.x);
            ((uint32_t*)bs)[v * 4 + 1] = tf32u(b4.y);
            ((uint32_t*)bs)[v * 4 + 2] = tf32u(b4.z);
            ((uint32_t*)bs)[v * 4 + 3] = tf32u(b4.w);
        }
    }
    __syncthreads();

    for (int c = 0; c < NC; c++) {
        const int p = c & 1;

        // prefetch next chunk into registers
        float4 pa[2], pb[2];
        if (c + 1 < NC) {
            const float* ap = gA + (size_t)lrow * K + (c + 1) * BK + lc0;
            const float* bp = gB + (size_t)lrow * K + (c + 1) * BK + lc0;
            #pragma unroll
            for (int v = 0; v < 2; v++) {
                pa[v] = *(const float4*)(ap + v * 8 + (v ? 4 : 0));
            }
            // load all 4 float4s (use two arrays of 2 to keep regs tight)
            pa[0] = *(const float4*)(ap + 0);
            pa[1] = *(const float4*)(ap + 4);
            pb[0] = *(const float4*)(ap + 8);
            pb[1] = *(const float4*)(ap + 12);
            // B handled below after compute (reload; L1-hit)
            (void)bp;
        }

        // ---- compute chunk c ----
        const uint32_t* as = (const uint32_t*)(As[p]);
        const uint32_t* bs = (const uint32_t*)(Bs[p]);
        #pragma unroll
        for (int ks = 0; ks < 4; ks++) {
            const int k = ks * 8;
            uint32_t af[2][4];
            #pragma unroll
            for (int mt = 0; mt < 2; mt++) {
                int r0 = wm * 32 + mt * 16 + grp;
                af[mt][0] = as[r0 * SSTR + k + quad];
                af[mt][1] = as[(r0 + 8) * SSTR + k + quad];
                af[mt][2] = as[r0 * SSTR + k + 4 + quad];
                af[mt][3] = as[(r0 + 8) * SSTR + k + 4 + quad];
            }
            #pragma unroll
            for (int nt = 0; nt < 8; nt++) {
                int ncol = wn * 64 + nt * 8 + grp;
                uint32_t bf[2];
                bf[0] = bs[ncol * SSTR + k + quad];
                bf[1] = bs[ncol * SSTR + k + 4 + quad];
                mma16n8k8(acc[0][nt], af[0], bf);
                mma16n8k8(acc[1][nt], af[1], bf);
            }
        }

        // ---- store prefetched chunk into other buffer ----
        if (c + 1 < NC) {
            float* asw = As[1 - p] + lrow * SSTR + lc0;
            float* bsw = Bs[1 - p] + lrow * SSTR + lc0;
            ((uint32_t*)asw)[0] = tf32u(pa[0].x); ((uint32_t*)asw)[1] = tf32u(pa[0].y);
            ((uint32_t*)asw)[2] = tf32u(pa[0].z); ((uint32_t*)asw)[3] = tf32u(pa[0].w);
            ((uint32_t*)asw)[4] = tf32u(pa[1].x); ((uint32_t*)asw)[5] = tf32u(pa[1].y);
            ((uint32_t*)asw)[6] = tf32u(pa[1].z); ((uint32_t*)asw)[7] = tf32u(pa[1].w);
            ((uint32_t*)asw)[8]  = tf32u(pb[0].x); ((uint32_t*)asw)[9]  = tf32u(pb[0].y);
            ((uint32_t*)asw)[10] = tf32u(pb[0].z); ((uint32_t*)asw)[11] = tf32u(pb[0].w);
            ((uint32_t*)asw)[12] = tf32u(pb[1].x); ((uint32_t*)asw)[13] = tf32u(pb[1].y);
            ((uint32_t*)asw)[14] = tf32u(pb[1].z); ((uint32_t*)asw)[15] = tf32u(pb[1].w);
            // B tile: straight load (L2/L1 resident for weights)
            const float* bp = gB + (size_t)lrow * K + (c + 1) * BK + lc0;
            #pragma unroll
            for (int v = 0; v < 4; v++) {
                float4 b4 = *(const float4*)(bp + v * 4);
                ((uint32_t*)bsw)[v * 4 + 0] = tf32u(b4.x);
                ((uint32_t*)bsw)[v * 4 + 1] = tf32u(b4.y);
                ((uint32_t*)bsw)[v * 4 + 2] = tf32u(b4.z);
                ((uint32_t*)bsw)[v * 4 + 3] = tf32u(b4.w);
            }
        }
        __syncthreads();
    }

    // ---- epilogue ----
    #pragma unroll
    for (int mt = 0; mt < 2; mt++) {
        int r0 = m0 + wm * 32 + mt * 16 + grp;
        #pragma unroll
        for (int nt = 0; nt < 8; nt++) {
            int col = n0 + wn * 64 + nt * 8 + 2 * quad;
            float b0 = 0.f, b1 = 0.f;
            if (BIAS) { b0 = bias[col]; b1 = bias[col + 1]; }
            float2 o0 = {acc[mt][nt][0] + b0, acc[mt][nt][1] + b1};
            float2 o1 = {acc[mt][nt][2] + b0, acc[mt][nt][3] + b1};
            *(float2*)&C[(size_t)r0 * N + col] = o0;
            *(float2*)&C[(size_t)(r0 + 8) * N + col] = o1;
        }
    }
}

// ============================================================================
// Flash attention (fp32, online softmax) — unchanged from R1.
// ============================================================================
#define TSTR 68
#define TILE_FLOATS (64 * TSTR)

__global__ __launch_bounds__(256) void attn_kernel(
    const float* __restrict__ qkv, float* __restrict__ out)
{
    extern __shared__ float sm[];
    float* Qs = sm;
    float* Ks = Qs + TILE_FLOATS;
    float* Vs = Ks + TILE_FLOATS;
    float* Ss = Vs + TILE_FLOATS;
    float* m_s = Ss + TILE_FLOATS;
    float* l_s = m_s + 64;
    float* al_s = l_s + 64;
    float* red = al_s + 64;

    const int b  = blockIdx.z;
    const int h  = blockIdx.y;
    const int q0 = blockIdx.x * 64;

    const int tid = threadIdx.x;
    const int tx = tid & 15;
    const int ty = tid >> 4;
    const int row = tid & 63;
    const int seg = tid >> 6;

    const float* qbase = qkv + ((size_t)(b * SEQ + q0)) * (3 * DIM) + h * HDIM;
    for (int i = tid; i < 64 * 16; i += 256) {
        int r = i >> 4;
        int c4 = (i & 15) << 2;
        float4 v = *(const float4*)(qbase + (size_t)r * (3 * DIM) + c4);
        Qs[(c4 + 0) * TSTR + r] = v.x * QK_SCALE;
        Qs[(c4 + 1) * TSTR + r] = v.y * QK_SCALE;
        Qs[(c4 + 2) * TSTR + r] = v.z * QK_SCALE;
        Qs[(c4 + 3) * TSTR + r] = v.w * QK_SCALE;
    }
    if (tid < 64) { m_s[tid] = -1e30f; l_s[tid] = 0.f; }

    float acc[4][4] = {};
    __syncthreads();

    for (int kt = 0; kt < SEQ / 64; kt++) {
        const int k0 = kt * 64;
        const float* kbase = qkv + ((size_t)(b * SEQ + k0)) * (3 * DIM) + DIM + h * HDIM;
        const float* vbase = kbase + DIM;

        for (int i = tid; i < 64 * 16; i += 256) {
            int r = i >> 4;
            int c4 = (i & 15) << 2;
            float4 kv = *(const float4*)(kbase + (size_t)r * (3 * DIM) + c4);
            Ks[(c4 + 0) * TSTR + r] = kv.x;
            Ks[(c4 + 1) * TSTR + r] = kv.y;
            Ks[(c4 + 2) * TSTR + r] = kv.z;
            Ks[(c4 + 3) * TSTR + r] = kv.w;
            float4 vv = *(const float4*)(vbase + (size_t)r * (3 * DIM) + c4);
            *(float4*)&Vs[r * TSTR + c4] = vv;
        }
        __syncthreads();

        float s[4][4] = {};
        #pragma unroll 8
        for (int k = 0; k < 64; k++) {
            float4 qa = *(const float4*)&Qs[k * TSTR + ty * 4];
            float4 kb = *(const float4*)&Ks[k * TSTR + tx * 4];
            float qr[4] = {qa.x, qa.y, qa.z, qa.w};
            float kr[4] = {kb.x, kb.y, kb.z, kb.w};
            #pragma unroll
            for (int i = 0; i < 4; i++)
                #pragma unroll
                for (int j = 0; j < 4; j++)
                    s[i][j] = fmaf(qr[i], kr[j], s[i][j]);
        }
        #pragma unroll
        for (int j = 0; j < 4; j++) {
            float4 o; o.x = s[0][j]; o.y = s[1][j]; o.z = s[2][j]; o.w = s[3][j];
            *(float4*)&Ss[(tx * 4 + j) * TSTR + ty * 4] = o;
        }
        __syncthreads();

        float lm = -1e30f;
        #pragma unroll
        for (int c = 0; c < 16; c++)
            lm = fmaxf(lm, Ss[(seg * 16 + c) * TSTR + row]);
        red[seg * 64 + row] = lm;
        __syncthreads();
        if (tid < 64) {
            float mt = fmaxf(fmaxf(red[tid], red[64 + tid]),
                             fmaxf(red[128 + tid], red[192 + tid]));
            float mold = m_s[tid];
            float mnew = fmaxf(mold, mt);
            m_s[tid]  = mnew;
            al_s[tid] = __expf(mold - mnew);
        }
        __syncthreads();

        float mnew = m_s[row];
        float ls = 0.f;
        #pragma unroll
        for (int c = 0; c < 16; c++) {
            int idx = (seg * 16 + c) * TSTR + row;
            float p = expf(Ss[idx] - mnew);
            Ss[idx] = p;
            ls += p;
        }
        red[seg * 64 + row] = ls;
        __syncthreads();
        if (tid < 64) {
            l_s[tid] = l_s[tid] * al_s[tid]
                     + red[tid] + red[64 + tid] + red[128 + tid] + red[192 + tid];
        }
        __syncthreads();

        float al[4];
        #pragma unroll
        for (int i = 0; i < 4; i++) al[i] = al_s[ty * 4 + i];
        #pragma unroll
        for (int i = 0; i < 4; i++)
            #pragma unroll
            for (int j = 0; j < 4; j++)
                acc[i][j] *= al[i];

        #pragma unroll 8
        for (int k = 0; k < 64; k++) {
            float4 pa = *(const float4*)&Ss[k * TSTR + ty * 4];
            float4 vb = *(const float4*)&Vs[k * TSTR + tx * 4];
            float pr[4] = {pa.x, pa.y, pa.z, pa.w};
            float vr[4] = {vb.x, vb.y, vb.z, vb.w};
            #pragma unroll
            for (int i = 0; i < 4; i++)
                #pragma unroll
                for (int j = 0; j < 4; j++)
                    acc[i][j] = fmaf(pr[i], vr[j], acc[i][j]);
        }
        __syncthreads();
    }

    #pragma unroll
    for (int i = 0; i < 4; i++) {
        float inv = 1.f / l_s[ty * 4 + i];
        float4 o;
        o.x = acc[i][0] * inv; o.y = acc[i][1] * inv;
        o.z = acc[i][2] * inv; o.w = acc[i][3] * inv;
        *(float4*)&out[(size_t)(b * SEQ + q0 + ty * 4 + i) * DIM + h * HDIM + tx * 4] = o;
    }
}

// ============================================================================
extern "C" void kernel_launch(void* const* d_in, const int* in_sizes, int n_in,
                              void* d_out, int out_size)
{
    const float* x     = (const float*)d_in[0];
    const float* w_qkv = (const float*)d_in[1];
    const float* w_out = (const float*)d_in[2];
    const float* b_out = (const float*)d_in[3];
    float* out = (float*)d_out;

    float* qkv = nullptr;
    float* att = nullptr;
    cudaGetSymbolAddress((void**)&qkv, g_qkv);
    cudaGetSymbolAddress((void**)&att, g_attn);

    const int attn_smem = (4 * TILE_FLOATS + 3 * 64 + 4 * 64) * (int)sizeof(float);
    cudaFuncSetAttribute(attn_kernel, cudaFuncAttributeMaxDynamicSharedMemorySize,
                         attn_smem);
    cudaFuncSetAttribute(gemm_mma<false>, cudaFuncAttributeMaxDynamicSharedMemorySize,
                         GEMM_SMEM_BYTES);
    cudaFuncSetAttribute(gemm_mma<true>, cudaFuncAttributeMaxDynamicSharedMemorySize,
                         GEMM_SMEM_BYTES);

    // 1) qkv = x @ w_qkv^T : M=8192, N=3072, K=1024
    {
        dim3 grid(3 * DIM / 128, ROWS_TOTAL / 128);
        gemm_mma<false><<<grid, 256, GEMM_SMEM_BYTES>>>(x, w_qkv, nullptr, qkv,
                                                        3 * DIM, DIM);
    }
    // 2) flash attention
    {
        dim3 grid(SEQ / 64, HEADS, BATCH);
        attn_kernel<<<grid, 256, attn_smem>>>(qkv, att);
    }
    // 3) out = att @ w_out^T + b_out : M=8192, N=1024, K=1024
    {
        dim3 grid(DIM / 128, ROWS_TOTAL / 128);
        gemm_mma<true><<<grid, 256, GEMM_SMEM_BYTES>>>(att, w_out, b_out, out,
                                                       DIM, DIM);
    }
}